// round 14
// baseline (speedup 1.0000x reference)
#include <cuda_runtime.h>

#define NTOK 20
#define NI   40          // instances per row: [b0 tok0..19 | b1 tok0..19], 160B rows
#define TPB  128
#define MAXCTAS 16384
#define SCRATCH_STRIDE 4096   // floats per CTA (100 rows x 40, padded to 16KB)

typedef unsigned long long ull;

// global scratch for the fused stage's m2-hidden output (per-CTA slot)
__device__ __align__(16) float g_m2h[(size_t)MAXCTAS * SCRATCH_STRIDE];

// ---------- packed f32x2 helpers ----------
__device__ __forceinline__ ull pk2(float lo, float hi) {
    ull r;
    asm("mov.b64 %0, {%1,%2};" : "=l"(r)
        : "r"(__float_as_uint(lo)), "r"(__float_as_uint(hi)));
    return r;
}
__device__ __forceinline__ void upk2(ull v, float& lo, float& hi) {
    unsigned int a, b;
    asm("mov.b64 {%0,%1}, %2;" : "=r"(a), "=r"(b) : "l"(v));
    lo = __uint_as_float(a); hi = __uint_as_float(b);
}
__device__ __forceinline__ void fma2(ull& d, ull a, ull b) {
    asm("fma.rn.f32x2 %0, %1, %2, %0;" : "+l"(d) : "l"(a), "l"(b));
}

// ---------- dense layer over 2 blocked batches ----------
// in may be smem or global (generic loads). rows [F][NI].
template<int FI, int FO, int WS, int JT, bool RELU, int BMODE>
__device__ __forceinline__ void dense(const float* __restrict__ W,
                                      const void* __restrict__ Bv,
                                      const float* in_sh, float* out_sh) {
    static_assert(FO % JT == 0, "FO divisible by JT");
    constexpr int U = (FO / JT) * 5;
    const int tid = threadIdx.x;
    for (int u = tid; u < U; u += TPB) {
        const int q  = u / 5;
        const int tg = u % 5;
        const int j0 = q * JT;
        float* op0 = out_sh + j0 * NI + 4 * tg;
        ull acc[JT][4];
        #pragma unroll
        for (int j = 0; j < JT; j++) {
            if constexpr (BMODE == 2) {
                const float* op = op0 + j * NI;
                const ulonglong2 p0 = *reinterpret_cast<const ulonglong2*>(op);
                const ulonglong2 p1 = *reinterpret_cast<const ulonglong2*>(op + 20);
                acc[j][0] = p0.x; acc[j][1] = p0.y;
                acc[j][2] = p1.x; acc[j][3] = p1.y;
            } else if constexpr (BMODE == 1) {
                const ull bb = reinterpret_cast<const ull*>(Bv)[j0 + j];
                float blo, bhi; upk2(bb, blo, bhi);
                acc[j][0] = acc[j][1] = pk2(blo, blo);
                acc[j][2] = acc[j][3] = pk2(bhi, bhi);
            } else {
                const float b = reinterpret_cast<const float*>(Bv)[j0 + j];
                const ull bb = pk2(b, b);
                #pragma unroll
                for (int pg = 0; pg < 4; pg++) acc[j][pg] = bb;
            }
        }
        const float* wp = W + j0;
        const float* ip = in_sh + 4 * tg;
        #pragma unroll 4
        for (int i = 0; i < FI; i++) {
            const ulonglong2 v0 = *reinterpret_cast<const ulonglong2*>(ip + i * NI);
            const ulonglong2 v1 = *reinterpret_cast<const ulonglong2*>(ip + i * NI + 20);
            float w[JT];
            if constexpr (JT == 4) {
                const float4 wv = *reinterpret_cast<const float4*>(wp + i * WS);
                w[0] = wv.x; w[1] = wv.y; w[2] = wv.z; w[3] = wv.w;
            } else {
                #pragma unroll
                for (int jj = 0; jj < JT / 2; jj++) {
                    const float2 wv =
                        *reinterpret_cast<const float2*>(wp + i * WS + 2 * jj);
                    w[2 * jj] = wv.x; w[2 * jj + 1] = wv.y;
                }
            }
            #pragma unroll
            for (int j = 0; j < JT; j++) {
                const ull wd = pk2(w[j], w[j]);
                fma2(acc[j][0], v0.x, wd);
                fma2(acc[j][1], v0.y, wd);
                fma2(acc[j][2], v1.x, wd);
                fma2(acc[j][3], v1.y, wd);
            }
        }
        #pragma unroll
        for (int j = 0; j < JT; j++) {
            if (RELU) {
                #pragma unroll
                for (int pg = 0; pg < 4; pg++) {
                    float a, b; upk2(acc[j][pg], a, b);
                    acc[j][pg] = pk2(fmaxf(a, 0.f), fmaxf(b, 0.f));
                }
            }
            ulonglong2 s0, s1;
            s0.x = acc[j][0]; s0.y = acc[j][1];
            s1.x = acc[j][2]; s1.y = acc[j][3];
            float* op = op0 + j * NI;
            *reinterpret_cast<ulonglong2*>(op)      = s0;
            *reinterpret_cast<ulonglong2*>(op + 20) = s1;
        }
    }
}

// ---------- fused pass: out1 = relu(W1.in + b1) [-> global], out2 = relu(W2.in + fold2) ----------
template<int FI, int FO>
__device__ __forceinline__ void dense_fused(const float* __restrict__ W1,
                                            const float* __restrict__ Bv1,
                                            const float* __restrict__ W2,
                                            const ull* __restrict__ fold2,
                                            const float* in_sh,
                                            float* out1, float* out2) {
    constexpr int U = (FO / 4) * 5;
    const int tid = threadIdx.x;
    for (int u = tid; u < U; u += TPB) {
        const int q  = u / 5;
        const int tg = u % 5;
        const int j0 = 4 * q;
        ull a1[4][4], a2[4][4];
        #pragma unroll
        for (int j = 0; j < 4; j++) {
            const float b = Bv1[j0 + j];
            const ull bb = pk2(b, b);
            #pragma unroll
            for (int pg = 0; pg < 4; pg++) a1[j][pg] = bb;
            float lo, hi; upk2(fold2[j0 + j], lo, hi);
            a2[j][0] = a2[j][1] = pk2(lo, lo);
            a2[j][2] = a2[j][3] = pk2(hi, hi);
        }
        const float* ip = in_sh + 4 * tg;
        #pragma unroll 2
        for (int i = 0; i < FI; i++) {
            const ulonglong2 v0 = *reinterpret_cast<const ulonglong2*>(ip + i * NI);
            const ulonglong2 v1 = *reinterpret_cast<const ulonglong2*>(ip + i * NI + 20);
            const float4 w1 = *reinterpret_cast<const float4*>(W1 + i * FO + j0);
            const float4 w2 = *reinterpret_cast<const float4*>(W2 + i * FO + j0);
            const float wa1[4] = {w1.x, w1.y, w1.z, w1.w};
            const float wa2[4] = {w2.x, w2.y, w2.z, w2.w};
            #pragma unroll
            for (int j = 0; j < 4; j++) {
                const ull d1 = pk2(wa1[j], wa1[j]);
                fma2(a1[j][0], v0.x, d1); fma2(a1[j][1], v0.y, d1);
                fma2(a1[j][2], v1.x, d1); fma2(a1[j][3], v1.y, d1);
                const ull d2 = pk2(wa2[j], wa2[j]);
                fma2(a2[j][0], v0.x, d2); fma2(a2[j][1], v0.y, d2);
                fma2(a2[j][2], v1.x, d2); fma2(a2[j][3], v1.y, d2);
            }
        }
        #pragma unroll
        for (int j = 0; j < 4; j++) {
            #pragma unroll
            for (int pg = 0; pg < 4; pg++) {
                float a, b;
                upk2(a1[j][pg], a, b);
                a1[j][pg] = pk2(fmaxf(a, 0.f), fmaxf(b, 0.f));
                upk2(a2[j][pg], a, b);
                a2[j][pg] = pk2(fmaxf(a, 0.f), fmaxf(b, 0.f));
            }
            float* o1 = out1 + (j0 + j) * NI + 4 * tg;
            float* o2 = out2 + (j0 + j) * NI + 4 * tg;
            ulonglong2 s;
            s.x = a1[j][0]; s.y = a1[j][1];
            *reinterpret_cast<ulonglong2*>(o1) = s;
            s.x = a1[j][2]; s.y = a1[j][3];
            *reinterpret_cast<ulonglong2*>(o1 + 20) = s;
            s.x = a2[j][0]; s.y = a2[j][1];
            *reinterpret_cast<ulonglong2*>(o2) = s;
            s.x = a2[j][2]; s.y = a2[j][3];
            *reinterpret_cast<ulonglong2*>(o2 + 20) = s;
        }
    }
}

// ---------- vectorized two-stage fold ----------
template<int F1, int FG, int FO>
__device__ __forceinline__ void fold_bias_v(const float* __restrict__ W,
                                            const float* __restrict__ Bv,
                                            const ull* gv2, ull* fold2,
                                            ull* scratch) {
    constexpr int IC = 5;
    constexpr int CH = FG / IC;
    constexpr int U  = (FO / 4) * IC;
    const int tid = threadIdx.x;
    for (int u = tid; u < U; u += TPB) {
        const int q = u / IC, ic = u % IC;
        const int j0 = 4 * q, i0 = ic * CH;
        ull acc[4] = {0, 0, 0, 0};
        #pragma unroll
        for (int k = 0; k < CH; k++) {
            const int i = i0 + k;
            const float4 wv = *reinterpret_cast<const float4*>(W + (F1 + i) * FO + j0);
            const ull g = gv2[i];
            fma2(acc[0], g, pk2(wv.x, wv.x));
            fma2(acc[1], g, pk2(wv.y, wv.y));
            fma2(acc[2], g, pk2(wv.z, wv.z));
            fma2(acc[3], g, pk2(wv.w, wv.w));
        }
        #pragma unroll
        for (int jj = 0; jj < 4; jj++) scratch[u * 4 + jj] = acc[jj];
    }
    __syncthreads();
    if (tid < FO) {
        const int q = tid / 4, jj = tid % 4;
        const float b = Bv[tid];
        ull acc = pk2(b, b);
        const ull one = pk2(1.f, 1.f);
        #pragma unroll
        for (int ic = 0; ic < IC; ic++)
            fma2(acc, scratch[(q * IC + ic) * 4 + jj], one);
        fold2[tid] = acc;
    }
}

// smem layout (floats): A(100 rows) + B(100 rows) + C(50 rows) + misc = 42.5KB
#define OFF_A    0
#define OFF_B    (OFF_A + 100 * NI)
#define OFF_C    (OFF_B + 100 * NI)
#define OFF_G2   (OFF_C + 50 * NI)      // 100 ull = 200 floats
#define OFF_FOLD (OFF_G2 + 200)         // 100 ull = 200 floats
#define OFF_WS2  (OFF_FOLD + 200)       // 50 ull = 100 floats
#define OFF_MASK (OFF_WS2 + 100)
#define OFF_SE   (OFF_MASK + NI)
#define OFF_W    (OFF_SE + NI)
#define SMEM_FLOATS (OFF_W + NI)
#define SMEM_BYTES (SMEM_FLOATS * 4)

__global__ void __launch_bounds__(TPB, 5)
sp_kernel(const float* __restrict__ state,
          const float* __restrict__ m1w0, const float* __restrict__ m1b0,
          const float* __restrict__ m1w1, const float* __restrict__ m1b1,
          const float* __restrict__ m2w0, const float* __restrict__ m2b0,
          const float* __restrict__ m2w1, const float* __restrict__ m2b1,
          const float* __restrict__ atw0, const float* __restrict__ atb0,
          const float* __restrict__ atw1, const float* __restrict__ atb1,
          const float* __restrict__ atw2, const float* __restrict__ atb2,
          const float* __restrict__ hpw0, const float* __restrict__ hpb0,
          const float* __restrict__ hpw1, const float* __restrict__ hpb1,
          const float* __restrict__ hpw2, const float* __restrict__ hpb2,
          float* __restrict__ out)
{
    extern __shared__ __align__(16) float sm[];
    float* A       = sm + OFF_A;     // h1; at1 out (atH2); hp1 out (hpH2)
    float* B       = sm + OFF_B;     // m1 tb; fold scratch; ath; hp0 out (hpH)
    float* C       = sm + OFF_C;     // x; then h2
    ull*   g2_sh   = reinterpret_cast<ull*>(sm + OFF_G2);
    ull*   fold2   = reinterpret_cast<ull*>(sm + OFF_FOLD);
    ull*   ws2_sh  = reinterpret_cast<ull*>(sm + OFF_WS2);
    float* mask_sh = sm + OFF_MASK;
    float* se_sh   = sm + OFF_SE;
    float* w_sh    = sm + OFF_W;
    ull*   scratchB = reinterpret_cast<ull*>(B);   // fold scratch (B dead then)

    const int tid = threadIdx.x;
    const int b0  = 2 * blockIdx.x;
    float* m2h = g_m2h + (size_t)blockIdx.x * SCRATCH_STRIDE;  // global spill

    // ---- load 2 batches of state: blocked layout [b0 | b1], feature-major, x -> C ----
    const float* st = state + (size_t)b0 * (NTOK * 14);
    for (int t = tid; t < 2 * NTOK * 14; t += TPB) {
        const int bi = t / (NTOK * 14);
        const int r  = t - bi * (NTOK * 14);
        const int n  = r / 14, d = r % 14;
        const float v = st[(size_t)bi * (NTOK * 14) + r];
        if (d == 13) mask_sh[bi * NTOK + n] = v;
        else         C[d * NI + bi * NTOK + n] = v;
    }
    __syncthreads();

    // ---- m1 in 3 chunks of 50: tb = relu(W0 chunk) in B, A += W1 chunk . tb ----
    dense<13, 50, 150, 2, true, 0>(m1w0 +   0, m1b0 +   0, C, B);
    __syncthreads();
    dense<50, 100, 100, 4, false, 0>(m1w1 +    0, m1b1, B, A);
    __syncthreads();
    dense<13, 50, 150, 2, true, 0>(m1w0 +  50, m1b0 +  50, C, B);
    __syncthreads();
    dense<50, 100, 100, 4, false, 2>(m1w1 + 5000, (const void*)0, B, A);
    __syncthreads();
    dense<13, 50, 150, 2, true, 0>(m1w0 + 100, m1b0 + 100, C, B);
    __syncthreads();
    dense<50, 100, 100, 4, true, 2>(m1w1 + 10000, (const void*)0, B, A);
    __syncthreads();
    // A = h1; x (C) dead; B (tb) dead

    // ---- masked mean of h1 -> g2 packed (b0,b1) ----
    if (tid < 100) {
        const ull* mp = reinterpret_cast<const ull*>(mask_sh);
        const ull* hp = reinterpret_cast<const ull*>(A + tid * NI);
        const ull one = pk2(1.f, 1.f);
        float g[2];
        #pragma unroll
        for (int bi = 0; bi < 2; bi++) {
            ull macc = 0, acc = 0;
            #pragma unroll
            for (int k = 0; k < 10; k++) {
                fma2(macc, mp[bi * 10 + k], one);
                fma2(acc,  hp[bi * 10 + k], mp[bi * 10 + k]);
            }
            float a, b; upk2(macc, a, b);
            const float ms = a + b;
            upk2(acc, a, b);
            g[bi] = (ms > 0.f) ? (a + b) * (1.f / ms) : 0.f;
        }
        g2_sh[tid] = pk2(g[0], g[1]);
    }
    __syncthreads();

    // ---- fold at0's global half (scratch in dead B) ----
    fold_bias_v<100, 100, 100>(atw0, atb0, g2_sh, fold2, scratchB);
    __syncthreads();

    // ---- FUSED: m2w0 (A -> global m2h) + at0 (A -> B), one read of h1 ----
    dense_fused<100, 100>(m2w0, m2b0, atw0, fold2, A, m2h, B);
    __syncthreads();
    // A (h1) dead

    // ---- m2w1: global m2h -> h2 in C[0:50]; at1: B (ath) -> A (atH2)
    //      (independent after the fused barrier; back-to-back overlaps
    //       m2h global latency with at1's FFMA stream) ----
    dense<100, 50, 50, 2, false, 0>(m2w1, m2b1, m2h, C);
    dense<100, 100, 100, 4, true, 0>(atw1, atb1, B, A);
    __syncthreads();

    // ---- attention scores from A: thread = instance-pair (20 units),
    //      1 LDS.64 + 1 LDG per packed FFMA2 (2 instances share both loads) ----
    if (tid < NI / 2) {
        const float b2 = atb2[0];
        ull acc = pk2(b2, b2);
        const ull* ip = reinterpret_cast<const ull*>(A) + tid;
        #pragma unroll 4
        for (int i = 0; i < 100; i++) {
            const float w = atw2[i];
            fma2(acc, ip[i * (NI / 2)], pk2(w, w));
        }
        float s0, s1; upk2(acc, s0, s1);
        s0 *= mask_sh[2 * tid];
        s1 *= mask_sh[2 * tid + 1];
        se_sh[2 * tid]     = (s0 != 0.f) ? expf(s0) : 0.f;
        se_sh[2 * tid + 1] = (s1 != 0.f) ? expf(s1) : 0.f;
    }
    __syncthreads();
    if (tid < NI) {
        const int bi = tid / NTOK;
        float ssum = 0.f;
        #pragma unroll
        for (int n = 0; n < NTOK; n++) ssum += se_sh[bi * NTOK + n];
        w_sh[tid] = (ssum > 0.f) ? se_sh[tid] / ssum : 0.f;
    }
    __syncthreads();

    // ---- weighted sum of h2 (C) -> ws2 packed (b0,b1) ----
    if (tid < 50) {
        const ull* hp = reinterpret_cast<const ull*>(C + tid * NI);
        const ull* wp = reinterpret_cast<const ull*>(w_sh);
        float r[2];
        #pragma unroll
        for (int bi = 0; bi < 2; bi++) {
            ull acc = 0;
            #pragma unroll
            for (int k = 0; k < 10; k++) fma2(acc, hp[bi * 10 + k], wp[bi * 10 + k]);
            float a, b; upk2(acc, a, b);
            r[bi] = a + b;
        }
        ws2_sh[tid] = pk2(r[0], r[1]);
    }
    __syncthreads();

    // ---- fold hp0's weighted-sum half (scratch in dead B: ath consumed) ----
    fold_bias_v<50, 50, 100>(hpw0, hpb0, ws2_sh, fold2, scratchB);
    __syncthreads();

    // ---- head: hp0: C (h2) -> B (fold bias), hp1: B -> A ----
    dense<50, 100, 100, 4, true, 1>(hpw0, fold2, C, B);
    __syncthreads();
    dense<100, 100, 100, 4, true, 0>(hpw1, hpb1, B, A);
    __syncthreads();

    // ---- final 100 -> 7 from A: thread = (batch, token-quad, neuron) = 70 units,
    //      1 LDS.128 + 1 LDG per 2 FFMA2 (4 instances share both loads) ----
    if (tid < 70) {
        const int bi = tid / 35;
        const int r  = tid % 35;
        const int k  = r / 7, j = r % 7;
        const float bj = hpb2[j];
        ull acc0 = pk2(bj, bj), acc1 = acc0;
        const float* ip = A + bi * NTOK + 4 * k;
        #pragma unroll 4
        for (int i = 0; i < 100; i++) {
            const ulonglong2 v = *reinterpret_cast<const ulonglong2*>(ip + i * NI);
            const float w = hpw2[i * 7 + j];
            const ull wd = pk2(w, w);
            fma2(acc0, v.x, wd);
            fma2(acc1, v.y, wd);
        }
        float a, b, c, d;
        upk2(acc0, a, b); upk2(acc1, c, d);
        float* ob = out + (size_t)(b0 + bi) * (NTOK * 7) + (4 * k) * 7 + j;
        ob[0]  = a;
        ob[7]  = b;
        ob[14] = c;
        ob[21] = d;
    }
}

extern "C" void kernel_launch(void* const* d_in, const int* in_sizes, int n_in,
                              void* d_out, int out_size) {
    cudaFuncSetAttribute(sp_kernel,
                         cudaFuncAttributeMaxDynamicSharedMemorySize, SMEM_BYTES);
    cudaFuncSetAttribute(sp_kernel,
                         cudaFuncAttributePreferredSharedMemoryCarveout, 100);

    // state is the only huge tensor (B*20*14 elems); detect its position by size.
    int si, wb;
    if (in_sizes[0] > 1000000) { si = 0;        wb = 1; }
    else                       { si = n_in - 1; wb = 0; }
    const float* state = (const float*)d_in[si];
    const int B = in_sizes[si] / (NTOK * 14);

    sp_kernel<<<B / 2, TPB, SMEM_BYTES>>>(
        state,
        (const float*)d_in[wb + 0],  (const float*)d_in[wb + 1],
        (const float*)d_in[wb + 2],  (const float*)d_in[wb + 3],
        (const float*)d_in[wb + 4],  (const float*)d_in[wb + 5],
        (const float*)d_in[wb + 6],  (const float*)d_in[wb + 7],
        (const float*)d_in[wb + 8],  (const float*)d_in[wb + 9],
        (const float*)d_in[wb + 10], (const float*)d_in[wb + 11],
        (const float*)d_in[wb + 12], (const float*)d_in[wb + 13],
        (const float*)d_in[wb + 14], (const float*)d_in[wb + 15],
        (const float*)d_in[wb + 16], (const float*)d_in[wb + 17],
        (const float*)d_in[wb + 18], (const float*)d_in[wb + 19],
        (float*)d_out);
}

// round 16
// speedup vs baseline: 1.0316x; 1.0316x over previous
#include <cuda_runtime.h>

#define NTOK 20
#define NI   40          // instances per row: [b0 tok0..19 | b1 tok0..19], 160B rows
#define TPB  128
#define MAXCTAS 16384
#define SCRATCH_STRIDE 4096   // floats per CTA (100 rows x 40, padded to 16KB)

typedef unsigned long long ull;

// global scratch for the fused stage's m2-hidden output (per-CTA slot)
__device__ __align__(16) float g_m2h[(size_t)MAXCTAS * SCRATCH_STRIDE];

// ---------- packed f32x2 helpers ----------
__device__ __forceinline__ ull pk2(float lo, float hi) {
    ull r;
    asm("mov.b64 %0, {%1,%2};" : "=l"(r)
        : "r"(__float_as_uint(lo)), "r"(__float_as_uint(hi)));
    return r;
}
__device__ __forceinline__ void upk2(ull v, float& lo, float& hi) {
    unsigned int a, b;
    asm("mov.b64 {%0,%1}, %2;" : "=r"(a), "=r"(b) : "l"(v));
    lo = __uint_as_float(a); hi = __uint_as_float(b);
}
__device__ __forceinline__ void fma2(ull& d, ull a, ull b) {
    asm("fma.rn.f32x2 %0, %1, %2, %0;" : "+l"(d) : "l"(a), "l"(b));
}

// ---------- dense layer over 2 blocked batches ----------
template<int FI, int FO, int WS, int JT, bool RELU, int BMODE>
__device__ __forceinline__ void dense(const float* __restrict__ W,
                                      const void* __restrict__ Bv,
                                      const float* in_sh, float* out_sh) {
    static_assert(FO % JT == 0, "FO divisible by JT");
    constexpr int U = (FO / JT) * 5;
    const int tid = threadIdx.x;
    for (int u = tid; u < U; u += TPB) {
        const int q  = u / 5;
        const int tg = u % 5;
        const int j0 = q * JT;
        float* op0 = out_sh + j0 * NI + 4 * tg;
        ull acc[JT][4];
        #pragma unroll
        for (int j = 0; j < JT; j++) {
            if constexpr (BMODE == 2) {
                const float* op = op0 + j * NI;
                const ulonglong2 p0 = *reinterpret_cast<const ulonglong2*>(op);
                const ulonglong2 p1 = *reinterpret_cast<const ulonglong2*>(op + 20);
                acc[j][0] = p0.x; acc[j][1] = p0.y;
                acc[j][2] = p1.x; acc[j][3] = p1.y;
            } else if constexpr (BMODE == 1) {
                const ull bb = reinterpret_cast<const ull*>(Bv)[j0 + j];
                float blo, bhi; upk2(bb, blo, bhi);
                acc[j][0] = acc[j][1] = pk2(blo, blo);
                acc[j][2] = acc[j][3] = pk2(bhi, bhi);
            } else {
                const float b = reinterpret_cast<const float*>(Bv)[j0 + j];
                const ull bb = pk2(b, b);
                #pragma unroll
                for (int pg = 0; pg < 4; pg++) acc[j][pg] = bb;
            }
        }
        const float* wp = W + j0;
        const float* ip = in_sh + 4 * tg;
        #pragma unroll 4
        for (int i = 0; i < FI; i++) {
            const ulonglong2 v0 = *reinterpret_cast<const ulonglong2*>(ip + i * NI);
            const ulonglong2 v1 = *reinterpret_cast<const ulonglong2*>(ip + i * NI + 20);
            float w[JT];
            if constexpr (JT == 4) {
                const float4 wv = *reinterpret_cast<const float4*>(wp + i * WS);
                w[0] = wv.x; w[1] = wv.y; w[2] = wv.z; w[3] = wv.w;
            } else {
                #pragma unroll
                for (int jj = 0; jj < JT / 2; jj++) {
                    const float2 wv =
                        *reinterpret_cast<const float2*>(wp + i * WS + 2 * jj);
                    w[2 * jj] = wv.x; w[2 * jj + 1] = wv.y;
                }
            }
            #pragma unroll
            for (int j = 0; j < JT; j++) {
                const ull wd = pk2(w[j], w[j]);
                fma2(acc[j][0], v0.x, wd);
                fma2(acc[j][1], v0.y, wd);
                fma2(acc[j][2], v1.x, wd);
                fma2(acc[j][3], v1.y, wd);
            }
        }
        #pragma unroll
        for (int j = 0; j < JT; j++) {
            if (RELU) {
                #pragma unroll
                for (int pg = 0; pg < 4; pg++) {
                    float a, b; upk2(acc[j][pg], a, b);
                    acc[j][pg] = pk2(fmaxf(a, 0.f), fmaxf(b, 0.f));
                }
            }
            ulonglong2 s0, s1;
            s0.x = acc[j][0]; s0.y = acc[j][1];
            s1.x = acc[j][2]; s1.y = acc[j][3];
            float* op = op0 + j * NI;
            *reinterpret_cast<ulonglong2*>(op)      = s0;
            *reinterpret_cast<ulonglong2*>(op + 20) = s1;
        }
    }
}

// ---------- fused pass: out1 = relu(W1.in + b1) [-> global], out2 = relu(W2.in + fold2) ----------
template<int FI, int FO>
__device__ __forceinline__ void dense_fused(const float* __restrict__ W1,
                                            const float* __restrict__ Bv1,
                                            const float* __restrict__ W2,
                                            const ull* __restrict__ fold2,
                                            const float* in_sh,
                                            float* out1, float* out2) {
    constexpr int U = (FO / 4) * 5;
    const int tid = threadIdx.x;
    for (int u = tid; u < U; u += TPB) {
        const int q  = u / 5;
        const int tg = u % 5;
        const int j0 = 4 * q;
        ull a1[4][4], a2[4][4];
        #pragma unroll
        for (int j = 0; j < 4; j++) {
            const float b = Bv1[j0 + j];
            const ull bb = pk2(b, b);
            #pragma unroll
            for (int pg = 0; pg < 4; pg++) a1[j][pg] = bb;
            float lo, hi; upk2(fold2[j0 + j], lo, hi);
            a2[j][0] = a2[j][1] = pk2(lo, lo);
            a2[j][2] = a2[j][3] = pk2(hi, hi);
        }
        const float* ip = in_sh + 4 * tg;
        #pragma unroll 2
        for (int i = 0; i < FI; i++) {
            const ulonglong2 v0 = *reinterpret_cast<const ulonglong2*>(ip + i * NI);
            const ulonglong2 v1 = *reinterpret_cast<const ulonglong2*>(ip + i * NI + 20);
            const float4 w1 = *reinterpret_cast<const float4*>(W1 + i * FO + j0);
            const float4 w2 = *reinterpret_cast<const float4*>(W2 + i * FO + j0);
            const float wa1[4] = {w1.x, w1.y, w1.z, w1.w};
            const float wa2[4] = {w2.x, w2.y, w2.z, w2.w};
            #pragma unroll
            for (int j = 0; j < 4; j++) {
                const ull d1 = pk2(wa1[j], wa1[j]);
                fma2(a1[j][0], v0.x, d1); fma2(a1[j][1], v0.y, d1);
                fma2(a1[j][2], v1.x, d1); fma2(a1[j][3], v1.y, d1);
                const ull d2 = pk2(wa2[j], wa2[j]);
                fma2(a2[j][0], v0.x, d2); fma2(a2[j][1], v0.y, d2);
                fma2(a2[j][2], v1.x, d2); fma2(a2[j][3], v1.y, d2);
            }
        }
        #pragma unroll
        for (int j = 0; j < 4; j++) {
            #pragma unroll
            for (int pg = 0; pg < 4; pg++) {
                float a, b;
                upk2(a1[j][pg], a, b);
                a1[j][pg] = pk2(fmaxf(a, 0.f), fmaxf(b, 0.f));
                upk2(a2[j][pg], a, b);
                a2[j][pg] = pk2(fmaxf(a, 0.f), fmaxf(b, 0.f));
            }
            float* o1 = out1 + (j0 + j) * NI + 4 * tg;
            float* o2 = out2 + (j0 + j) * NI + 4 * tg;
            ulonglong2 s;
            s.x = a1[j][0]; s.y = a1[j][1];
            *reinterpret_cast<ulonglong2*>(o1) = s;
            s.x = a1[j][2]; s.y = a1[j][3];
            *reinterpret_cast<ulonglong2*>(o1 + 20) = s;
            s.x = a2[j][0]; s.y = a2[j][1];
            *reinterpret_cast<ulonglong2*>(o2) = s;
            s.x = a2[j][2]; s.y = a2[j][3];
            *reinterpret_cast<ulonglong2*>(o2 + 20) = s;
        }
    }
}

// ---------- vectorized two-stage fold ----------
template<int F1, int FG, int FO>
__device__ __forceinline__ void fold_bias_v(const float* __restrict__ W,
                                            const float* __restrict__ Bv,
                                            const ull* gv2, ull* fold2,
                                            ull* scratch) {
    constexpr int IC = 5;
    constexpr int CH = FG / IC;
    constexpr int U  = (FO / 4) * IC;
    const int tid = threadIdx.x;
    for (int u = tid; u < U; u += TPB) {
        const int q = u / IC, ic = u % IC;
        const int j0 = 4 * q, i0 = ic * CH;
        ull acc[4] = {0, 0, 0, 0};
        #pragma unroll
        for (int k = 0; k < CH; k++) {
            const int i = i0 + k;
            const float4 wv = *reinterpret_cast<const float4*>(W + (F1 + i) * FO + j0);
            const ull g = gv2[i];
            fma2(acc[0], g, pk2(wv.x, wv.x));
            fma2(acc[1], g, pk2(wv.y, wv.y));
            fma2(acc[2], g, pk2(wv.z, wv.z));
            fma2(acc[3], g, pk2(wv.w, wv.w));
        }
        #pragma unroll
        for (int jj = 0; jj < 4; jj++) scratch[u * 4 + jj] = acc[jj];
    }
    __syncthreads();
    if (tid < FO) {
        const int q = tid / 4, jj = tid % 4;
        const float b = Bv[tid];
        ull acc = pk2(b, b);
        const ull one = pk2(1.f, 1.f);
        #pragma unroll
        for (int ic = 0; ic < IC; ic++)
            fma2(acc, scratch[(q * IC + ic) * 4 + jj], one);
        fold2[tid] = acc;
    }
}

// smem layout (floats): A(100 rows) + B(100 rows) + C(50 rows) + misc = 42.5KB
#define OFF_A    0
#define OFF_B    (OFF_A + 100 * NI)
#define OFF_C    (OFF_B + 100 * NI)
#define OFF_G2   (OFF_C + 50 * NI)      // 100 ull = 200 floats
#define OFF_FOLD (OFF_G2 + 200)         // 100 ull = 200 floats
#define OFF_WS2  (OFF_FOLD + 200)       // 50 ull = 100 floats
#define OFF_MASK (OFF_WS2 + 100)
#define OFF_SE   (OFF_MASK + NI)
#define OFF_W    (OFF_SE + NI)
#define SMEM_FLOATS (OFF_W + NI)
#define SMEM_BYTES (SMEM_FLOATS * 4)

__global__ void __launch_bounds__(TPB, 5)
sp_kernel(const float* __restrict__ state,
          const float* __restrict__ m1w0, const float* __restrict__ m1b0,
          const float* __restrict__ m1w1, const float* __restrict__ m1b1,
          const float* __restrict__ m2w0, const float* __restrict__ m2b0,
          const float* __restrict__ m2w1, const float* __restrict__ m2b1,
          const float* __restrict__ atw0, const float* __restrict__ atb0,
          const float* __restrict__ atw1, const float* __restrict__ atb1,
          const float* __restrict__ atw2, const float* __restrict__ atb2,
          const float* __restrict__ hpw0, const float* __restrict__ hpb0,
          const float* __restrict__ hpw1, const float* __restrict__ hpb1,
          const float* __restrict__ hpw2, const float* __restrict__ hpb2,
          float* __restrict__ out)
{
    extern __shared__ __align__(16) float sm[];
    float* A       = sm + OFF_A;     // h1; at1 out (atH2); hp1 out (hpH2)
    float* B       = sm + OFF_B;     // m1 tb; fold scratch; ath; hp0 out; tail partials
    float* C       = sm + OFF_C;     // x; then h2
    ull*   g2_sh   = reinterpret_cast<ull*>(sm + OFF_G2);
    ull*   fold2   = reinterpret_cast<ull*>(sm + OFF_FOLD);
    ull*   ws2_sh  = reinterpret_cast<ull*>(sm + OFF_WS2);
    float* mask_sh = sm + OFF_MASK;
    float* se_sh   = sm + OFF_SE;
    float* w_sh    = sm + OFF_W;
    ull*   scratchB = reinterpret_cast<ull*>(B);   // fold/tail scratch (B dead then)

    const int tid = threadIdx.x;
    const int b0  = 2 * blockIdx.x;
    float* m2h = g_m2h + (size_t)blockIdx.x * SCRATCH_STRIDE;  // global spill

    // ---- load 2 batches of state: blocked layout [b0 | b1], feature-major, x -> C ----
    const float* st = state + (size_t)b0 * (NTOK * 14);
    for (int t = tid; t < 2 * NTOK * 14; t += TPB) {
        const int bi = t / (NTOK * 14);
        const int r  = t - bi * (NTOK * 14);
        const int n  = r / 14, d = r % 14;
        const float v = st[(size_t)bi * (NTOK * 14) + r];
        if (d == 13) mask_sh[bi * NTOK + n] = v;
        else         C[d * NI + bi * NTOK + n] = v;
    }
    __syncthreads();

    // ---- m1 in 3 chunks of 50: tb = relu(W0 chunk) in B, A += W1 chunk . tb ----
    dense<13, 50, 150, 2, true, 0>(m1w0 +   0, m1b0 +   0, C, B);
    __syncthreads();
    dense<50, 100, 100, 4, false, 0>(m1w1 +    0, m1b1, B, A);
    __syncthreads();
    dense<13, 50, 150, 2, true, 0>(m1w0 +  50, m1b0 +  50, C, B);
    __syncthreads();
    dense<50, 100, 100, 4, false, 2>(m1w1 + 5000, (const void*)0, B, A);
    __syncthreads();
    dense<13, 50, 150, 2, true, 0>(m1w0 + 100, m1b0 + 100, C, B);
    __syncthreads();
    dense<50, 100, 100, 4, true, 2>(m1w1 + 10000, (const void*)0, B, A);
    __syncthreads();
    // A = h1; x (C) dead; B (tb) dead

    // ---- masked mean of h1 -> g2 packed (b0,b1) ----
    if (tid < 100) {
        const ull* mp = reinterpret_cast<const ull*>(mask_sh);
        const ull* hp = reinterpret_cast<const ull*>(A + tid * NI);
        const ull one = pk2(1.f, 1.f);
        float g[2];
        #pragma unroll
        for (int bi = 0; bi < 2; bi++) {
            ull macc = 0, acc = 0;
            #pragma unroll
            for (int k = 0; k < 10; k++) {
                fma2(macc, mp[bi * 10 + k], one);
                fma2(acc,  hp[bi * 10 + k], mp[bi * 10 + k]);
            }
            float a, b; upk2(macc, a, b);
            const float ms = a + b;
            upk2(acc, a, b);
            g[bi] = (ms > 0.f) ? (a + b) * (1.f / ms) : 0.f;
        }
        g2_sh[tid] = pk2(g[0], g[1]);
    }
    __syncthreads();

    // ---- fold at0's global half (scratch in dead B) ----
    fold_bias_v<100, 100, 100>(atw0, atb0, g2_sh, fold2, scratchB);
    __syncthreads();

    // ---- FUSED: m2w0 (A -> global m2h) + at0 (A -> B), one read of h1 ----
    dense_fused<100, 100>(m2w0, m2b0, atw0, fold2, A, m2h, B);
    __syncthreads();
    // A (h1) dead

    // ---- m2w1: global m2h -> h2 in C[0:50]; at1: B (ath) -> A (atH2)
    //      (independent after the fused barrier; back-to-back overlaps
    //       m2h global latency with at1's FFMA stream) ----
    dense<100, 50, 50, 2, false, 0>(m2w1, m2b1, m2h, C);
    dense<100, 100, 100, 4, true, 0>(atw1, atb1, B, A);
    __syncthreads();

    // ---- attention scores from A: i-split, 80 units x 50-step chains ----
    // partials in dead-B floats; then 40-lane combine.
    {
        float* part = B;   // ath consumed by at1 -> dead
        if (tid < 80) {
            const int half = tid / NI;        // 0: i 0..49, 1: i 50..99
            const int inst = tid % NI;
            const float* ip = A + inst + half * 50 * NI;
            float s = 0.f;
            #pragma unroll 5
            for (int i = 0; i < 50; i++)
                s = fmaf(ip[i * NI], atw2[half * 50 + i], s);
            part[tid] = s;
        }
        __syncthreads();
        if (tid < NI) {
            float s = part[tid] + part[tid + NI] + atb2[0];
            s *= mask_sh[tid];
            se_sh[tid] = (s != 0.f) ? __expf(s) : 0.f;
        }
    }
    __syncthreads();
    if (tid < NI) {
        const int bi = tid / NTOK;
        float ssum = 0.f;
        #pragma unroll
        for (int n = 0; n < NTOK; n++) ssum += se_sh[bi * NTOK + n];
        w_sh[tid] = (ssum > 0.f) ? se_sh[tid] / ssum : 0.f;
    }
    __syncthreads();

    // ---- weighted sum of h2 (C) -> ws2 packed (b0,b1) ----
    if (tid < 50) {
        const ull* hp = reinterpret_cast<const ull*>(C + tid * NI);
        const ull* wp = reinterpret_cast<const ull*>(w_sh);
        float r[2];
        #pragma unroll
        for (int bi = 0; bi < 2; bi++) {
            ull acc = 0;
            #pragma unroll
            for (int k = 0; k < 10; k++) fma2(acc, hp[bi * 10 + k], wp[bi * 10 + k]);
            float a, b; upk2(acc, a, b);
            r[bi] = a + b;
        }
        ws2_sh[tid] = pk2(r[0], r[1]);
    }
    __syncthreads();

    // ---- fold hp0's weighted-sum half (scratch in dead B: ath consumed) ----
    fold_bias_v<50, 50, 100>(hpw0, hpb0, ws2_sh, fold2, scratchB);
    __syncthreads();

    // ---- head: hp0: C (h2) -> B (fold bias), hp1: B -> A ----
    dense<50, 100, 100, 4, true, 1>(hpw0, fold2, C, B);
    __syncthreads();
    dense<100, 100, 100, 4, true, 0>(hpw1, hpb1, B, A);
    __syncthreads();

    // ---- final 100 -> 7 from A: i-split, 280 units x 50-step chains ----
    // partials (packed token-pairs) in dead-B ulls; 140-unit STRIDED combine
    // (140 > TPB: must loop — R5/R15 bug class).
    {
        ull* part = scratchB;   // B (hpH) consumed by hp1 -> dead
        for (int t = tid; t < 280; t += TPB) {
            const int half = t / 140;       // 0: i 0..49, 1: i 50..99
            const int r    = t % 140;
            const int bi = r / 70;
            const int rr = r % 70;
            const int k  = rr / 7, j = rr % 7;
            ull acc = 0;
            const ull* ip = reinterpret_cast<const ull*>(A) + bi * 10 + k
                            + half * 50 * (NI / 2);
            const float* wp = hpw2 + half * 50 * 7 + j;
            #pragma unroll 4
            for (int i = 0; i < 50; i++) {
                const float w = wp[i * 7];
                fma2(acc, ip[i * (NI / 2)], pk2(w, w));
            }
            part[t] = acc;
        }
        __syncthreads();
        for (int t = tid; t < 140; t += TPB) {
            const int bi = t / 70;
            const int rr = t % 70;
            const int k  = rr / 7, j = rr % 7;
            float a0, b0v, a1, b1v;
            upk2(part[t], a0, b0v);
            upk2(part[t + 140], a1, b1v);
            const float bj = hpb2[j];
            float* ob = out + (size_t)(b0 + bi) * (NTOK * 7);
            ob[(2 * k)     * 7 + j] = a0 + a1 + bj;
            ob[(2 * k + 1) * 7 + j] = b0v + b1v + bj;
        }
    }
}

extern "C" void kernel_launch(void* const* d_in, const int* in_sizes, int n_in,
                              void* d_out, int out_size) {
    cudaFuncSetAttribute(sp_kernel,
                         cudaFuncAttributeMaxDynamicSharedMemorySize, SMEM_BYTES);
    cudaFuncSetAttribute(sp_kernel,
                         cudaFuncAttributePreferredSharedMemoryCarveout, 100);

    // state is the only huge tensor (B*20*14 elems); detect its position by size.
    int si, wb;
    if (in_sizes[0] > 1000000) { si = 0;        wb = 1; }
    else                       { si = n_in - 1; wb = 0; }
    const float* state = (const float*)d_in[si];
    const int B = in_sizes[si] / (NTOK * 14);

    sp_kernel<<<B / 2, TPB, SMEM_BYTES>>>(
        state,
        (const float*)d_in[wb + 0],  (const float*)d_in[wb + 1],
        (const float*)d_in[wb + 2],  (const float*)d_in[wb + 3],
        (const float*)d_in[wb + 4],  (const float*)d_in[wb + 5],
        (const float*)d_in[wb + 6],  (const float*)d_in[wb + 7],
        (const float*)d_in[wb + 8],  (const float*)d_in[wb + 9],
        (const float*)d_in[wb + 10], (const float*)d_in[wb + 11],
        (const float*)d_in[wb + 12], (const float*)d_in[wb + 13],
        (const float*)d_in[wb + 14], (const float*)d_in[wb + 15],
        (const float*)d_in[wb + 16], (const float*)d_in[wb + 17],
        (const float*)d_in[wb + 18], (const float*)d_in[wb + 19],
        (float*)d_out);
}

// round 17
// speedup vs baseline: 1.0342x; 1.0025x over previous
#include <cuda_runtime.h>

#define NTOK 20
#define NI   40          // instances per row: [b0 tok0..19 | b1 tok0..19], 160B rows
#define TPB  128
#define MAXCTAS 16384
#define SCRATCH_STRIDE 4096   // floats per CTA (100 rows x 40, padded to 16KB)

typedef unsigned long long ull;

// global scratch for the fused stage's m2-hidden output (per-CTA slot)
__device__ __align__(16) float g_m2h[(size_t)MAXCTAS * SCRATCH_STRIDE];

// ---------- packed f32x2 helpers ----------
__device__ __forceinline__ ull pk2(float lo, float hi) {
    ull r;
    asm("mov.b64 %0, {%1,%2};" : "=l"(r)
        : "r"(__float_as_uint(lo)), "r"(__float_as_uint(hi)));
    return r;
}
__device__ __forceinline__ void upk2(ull v, float& lo, float& hi) {
    unsigned int a, b;
    asm("mov.b64 {%0,%1}, %2;" : "=r"(a), "=r"(b) : "l"(v));
    lo = __uint_as_float(a); hi = __uint_as_float(b);
}
__device__ __forceinline__ void fma2(ull& d, ull a, ull b) {
    asm("fma.rn.f32x2 %0, %1, %2, %0;" : "+l"(d) : "l"(a), "l"(b));
}

// ---------- dense layer over 2 blocked batches ----------
template<int FI, int FO, int WS, int JT, bool RELU, int BMODE>
__device__ __forceinline__ void dense(const float* __restrict__ W,
                                      const void* __restrict__ Bv,
                                      const float* in_sh, float* out_sh) {
    static_assert(FO % JT == 0, "FO divisible by JT");
    constexpr int U = (FO / JT) * 5;
    const int tid = threadIdx.x;
    for (int u = tid; u < U; u += TPB) {
        const int q  = u / 5;
        const int tg = u % 5;
        const int j0 = q * JT;
        float* op0 = out_sh + j0 * NI + 4 * tg;
        ull acc[JT][4];
        #pragma unroll
        for (int j = 0; j < JT; j++) {
            if constexpr (BMODE == 2) {
                const float* op = op0 + j * NI;
                const ulonglong2 p0 = *reinterpret_cast<const ulonglong2*>(op);
                const ulonglong2 p1 = *reinterpret_cast<const ulonglong2*>(op + 20);
                acc[j][0] = p0.x; acc[j][1] = p0.y;
                acc[j][2] = p1.x; acc[j][3] = p1.y;
            } else if constexpr (BMODE == 1) {
                const ull bb = reinterpret_cast<const ull*>(Bv)[j0 + j];
                float blo, bhi; upk2(bb, blo, bhi);
                acc[j][0] = acc[j][1] = pk2(blo, blo);
                acc[j][2] = acc[j][3] = pk2(bhi, bhi);
            } else {
                const float b = reinterpret_cast<const float*>(Bv)[j0 + j];
                const ull bb = pk2(b, b);
                #pragma unroll
                for (int pg = 0; pg < 4; pg++) acc[j][pg] = bb;
            }
        }
        const float* wp = W + j0;
        const float* ip = in_sh + 4 * tg;
        #pragma unroll 4
        for (int i = 0; i < FI; i++) {
            const ulonglong2 v0 = *reinterpret_cast<const ulonglong2*>(ip + i * NI);
            const ulonglong2 v1 = *reinterpret_cast<const ulonglong2*>(ip + i * NI + 20);
            float w[JT];
            if constexpr (JT == 4) {
                const float4 wv = *reinterpret_cast<const float4*>(wp + i * WS);
                w[0] = wv.x; w[1] = wv.y; w[2] = wv.z; w[3] = wv.w;
            } else {
                #pragma unroll
                for (int jj = 0; jj < JT / 2; jj++) {
                    const float2 wv =
                        *reinterpret_cast<const float2*>(wp + i * WS + 2 * jj);
                    w[2 * jj] = wv.x; w[2 * jj + 1] = wv.y;
                }
            }
            #pragma unroll
            for (int j = 0; j < JT; j++) {
                const ull wd = pk2(w[j], w[j]);
                fma2(acc[j][0], v0.x, wd);
                fma2(acc[j][1], v0.y, wd);
                fma2(acc[j][2], v1.x, wd);
                fma2(acc[j][3], v1.y, wd);
            }
        }
        #pragma unroll
        for (int j = 0; j < JT; j++) {
            if (RELU) {
                #pragma unroll
                for (int pg = 0; pg < 4; pg++) {
                    float a, b; upk2(acc[j][pg], a, b);
                    acc[j][pg] = pk2(fmaxf(a, 0.f), fmaxf(b, 0.f));
                }
            }
            ulonglong2 s0, s1;
            s0.x = acc[j][0]; s0.y = acc[j][1];
            s1.x = acc[j][2]; s1.y = acc[j][3];
            float* op = op0 + j * NI;
            *reinterpret_cast<ulonglong2*>(op)      = s0;
            *reinterpret_cast<ulonglong2*>(op + 20) = s1;
        }
    }
}

// ---------- fused pass: out1 = relu(W1.in + b1) [-> global], out2 = relu(W2.in + fold2) ----------
template<int FI, int FO>
__device__ __forceinline__ void dense_fused(const float* __restrict__ W1,
                                            const float* __restrict__ Bv1,
                                            const float* __restrict__ W2,
                                            const ull* __restrict__ fold2,
                                            const float* in_sh,
                                            float* out1, float* out2) {
    constexpr int U = (FO / 4) * 5;
    const int tid = threadIdx.x;
    for (int u = tid; u < U; u += TPB) {
        const int q  = u / 5;
        const int tg = u % 5;
        const int j0 = 4 * q;
        ull a1[4][4], a2[4][4];
        #pragma unroll
        for (int j = 0; j < 4; j++) {
            const float b = Bv1[j0 + j];
            const ull bb = pk2(b, b);
            #pragma unroll
            for (int pg = 0; pg < 4; pg++) a1[j][pg] = bb;
            float lo, hi; upk2(fold2[j0 + j], lo, hi);
            a2[j][0] = a2[j][1] = pk2(lo, lo);
            a2[j][2] = a2[j][3] = pk2(hi, hi);
        }
        const float* ip = in_sh + 4 * tg;
        #pragma unroll 2
        for (int i = 0; i < FI; i++) {
            const ulonglong2 v0 = *reinterpret_cast<const ulonglong2*>(ip + i * NI);
            const ulonglong2 v1 = *reinterpret_cast<const ulonglong2*>(ip + i * NI + 20);
            const float4 w1 = *reinterpret_cast<const float4*>(W1 + i * FO + j0);
            const float4 w2 = *reinterpret_cast<const float4*>(W2 + i * FO + j0);
            const float wa1[4] = {w1.x, w1.y, w1.z, w1.w};
            const float wa2[4] = {w2.x, w2.y, w2.z, w2.w};
            #pragma unroll
            for (int j = 0; j < 4; j++) {
                const ull d1 = pk2(wa1[j], wa1[j]);
                fma2(a1[j][0], v0.x, d1); fma2(a1[j][1], v0.y, d1);
                fma2(a1[j][2], v1.x, d1); fma2(a1[j][3], v1.y, d1);
                const ull d2 = pk2(wa2[j], wa2[j]);
                fma2(a2[j][0], v0.x, d2); fma2(a2[j][1], v0.y, d2);
                fma2(a2[j][2], v1.x, d2); fma2(a2[j][3], v1.y, d2);
            }
        }
        #pragma unroll
        for (int j = 0; j < 4; j++) {
            #pragma unroll
            for (int pg = 0; pg < 4; pg++) {
                float a, b;
                upk2(a1[j][pg], a, b);
                a1[j][pg] = pk2(fmaxf(a, 0.f), fmaxf(b, 0.f));
                upk2(a2[j][pg], a, b);
                a2[j][pg] = pk2(fmaxf(a, 0.f), fmaxf(b, 0.f));
            }
            float* o1 = out1 + (j0 + j) * NI + 4 * tg;
            float* o2 = out2 + (j0 + j) * NI + 4 * tg;
            ulonglong2 s;
            s.x = a1[j][0]; s.y = a1[j][1];
            *reinterpret_cast<ulonglong2*>(o1) = s;
            s.x = a1[j][2]; s.y = a1[j][3];
            *reinterpret_cast<ulonglong2*>(o1 + 20) = s;
            s.x = a2[j][0]; s.y = a2[j][1];
            *reinterpret_cast<ulonglong2*>(o2) = s;
            s.x = a2[j][2]; s.y = a2[j][3];
            *reinterpret_cast<ulonglong2*>(o2 + 20) = s;
        }
    }
}

// ---------- vectorized two-stage fold ----------
template<int F1, int FG, int FO>
__device__ __forceinline__ void fold_bias_v(const float* __restrict__ W,
                                            const float* __restrict__ Bv,
                                            const ull* gv2, ull* fold2,
                                            ull* scratch) {
    constexpr int IC = 5;
    constexpr int CH = FG / IC;
    constexpr int U  = (FO / 4) * IC;
    const int tid = threadIdx.x;
    for (int u = tid; u < U; u += TPB) {
        const int q = u / IC, ic = u % IC;
        const int j0 = 4 * q, i0 = ic * CH;
        ull acc[4] = {0, 0, 0, 0};
        #pragma unroll
        for (int k = 0; k < CH; k++) {
            const int i = i0 + k;
            const float4 wv = *reinterpret_cast<const float4*>(W + (F1 + i) * FO + j0);
            const ull g = gv2[i];
            fma2(acc[0], g, pk2(wv.x, wv.x));
            fma2(acc[1], g, pk2(wv.y, wv.y));
            fma2(acc[2], g, pk2(wv.z, wv.z));
            fma2(acc[3], g, pk2(wv.w, wv.w));
        }
        #pragma unroll
        for (int jj = 0; jj < 4; jj++) scratch[u * 4 + jj] = acc[jj];
    }
    __syncthreads();
    if (tid < FO) {
        const int q = tid / 4, jj = tid % 4;
        const float b = Bv[tid];
        ull acc = pk2(b, b);
        const ull one = pk2(1.f, 1.f);
        #pragma unroll
        for (int ic = 0; ic < IC; ic++)
            fma2(acc, scratch[(q * IC + ic) * 4 + jj], one);
        fold2[tid] = acc;
    }
}

// smem layout (floats): A(100 rows) + B(100 rows) + C(50 rows) + misc = 42.5KB
#define OFF_A    0
#define OFF_B    (OFF_A + 100 * NI)
#define OFF_C    (OFF_B + 100 * NI)
#define OFF_G2   (OFF_C + 50 * NI)      // 100 ull = 200 floats
#define OFF_FOLD (OFF_G2 + 200)         // 100 ull = 200 floats
#define OFF_WS2  (OFF_FOLD + 200)       // 50 ull = 100 floats
#define OFF_MASK (OFF_WS2 + 100)
#define OFF_SE   (OFF_MASK + NI)
#define OFF_W    (OFF_SE + NI)
#define SMEM_FLOATS (OFF_W + NI)
#define SMEM_BYTES (SMEM_FLOATS * 4)

__global__ void __launch_bounds__(TPB, 5)
sp_kernel(const float* __restrict__ state,
          const float* __restrict__ m1w0, const float* __restrict__ m1b0,
          const float* __restrict__ m1w1, const float* __restrict__ m1b1,
          const float* __restrict__ m2w0, const float* __restrict__ m2b0,
          const float* __restrict__ m2w1, const float* __restrict__ m2b1,
          const float* __restrict__ atw0, const float* __restrict__ atb0,
          const float* __restrict__ atw1, const float* __restrict__ atb1,
          const float* __restrict__ atw2, const float* __restrict__ atb2,
          const float* __restrict__ hpw0, const float* __restrict__ hpb0,
          const float* __restrict__ hpw1, const float* __restrict__ hpb1,
          const float* __restrict__ hpw2, const float* __restrict__ hpb2,
          float* __restrict__ out)
{
    extern __shared__ __align__(16) float sm[];
    float* A       = sm + OFF_A;     // h1; at1 out (atH2); hp1 out (hpH2)
    float* B       = sm + OFF_B;     // m1 tb (double-buffered halves); fold scratch; ath; hp0 out; tail partials
    float* C       = sm + OFF_C;     // x; then h2
    ull*   g2_sh   = reinterpret_cast<ull*>(sm + OFF_G2);
    ull*   fold2   = reinterpret_cast<ull*>(sm + OFF_FOLD);
    ull*   ws2_sh  = reinterpret_cast<ull*>(sm + OFF_WS2);
    float* mask_sh = sm + OFF_MASK;
    float* w_sh    = sm + OFF_W;
    ull*   scratchB = reinterpret_cast<ull*>(B);   // fold/tail scratch (B dead then)

    const int tid = threadIdx.x;
    const int b0  = 2 * blockIdx.x;
    float* m2h = g_m2h + (size_t)blockIdx.x * SCRATCH_STRIDE;  // global spill

    // ---- load 2 batches of state: blocked layout [b0 | b1], feature-major, x -> C ----
    const float* st = state + (size_t)b0 * (NTOK * 14);
    for (int t = tid; t < 2 * NTOK * 14; t += TPB) {
        const int bi = t / (NTOK * 14);
        const int r  = t - bi * (NTOK * 14);
        const int n  = r / 14, d = r % 14;
        const float v = st[(size_t)bi * (NTOK * 14) + r];
        if (d == 13) mask_sh[bi * NTOK + n] = v;
        else         C[d * NI + bi * NTOK + n] = v;
    }
    __syncthreads();

    // ---- m1 software-pipelined over 3 chunks of 50, tb double-buffered in B halves:
    //   S1: w0c0 -> B[0:50]
    //   S2: w1c0 (B[0:50] -> A, bias) + w0c1 -> B[50:100]     (disjoint halves)
    //   S3: w1c1 (B[50:100] -> A, acc) + w0c2 -> B[0:50]      (c0 half consumed pre-bar)
    //   S4: w1c2 (B[0:50] -> A, acc+relu)
    dense<13, 50, 150, 2, true, 0>(m1w0 + 0, m1b0 + 0, C, B);
    __syncthreads();
    dense<50, 100, 100, 4, false, 0>(m1w1 + 0, m1b1, B, A);
    dense<13, 50, 150, 2, true, 0>(m1w0 + 50, m1b0 + 50, C, B + 50 * NI);
    __syncthreads();
    dense<50, 100, 100, 4, false, 2>(m1w1 + 5000, (const void*)0, B + 50 * NI, A);
    dense<13, 50, 150, 2, true, 0>(m1w0 + 100, m1b0 + 100, C, B);
    __syncthreads();
    dense<50, 100, 100, 4, true, 2>(m1w1 + 10000, (const void*)0, B, A);
    __syncthreads();
    // A = h1; x (C) dead; B (tb) dead

    // ---- masked mean of h1 -> g2 packed (b0,b1) ----
    if (tid < 100) {
        const ull* mp = reinterpret_cast<const ull*>(mask_sh);
        const ull* hp = reinterpret_cast<const ull*>(A + tid * NI);
        const ull one = pk2(1.f, 1.f);
        float g[2];
        #pragma unroll
        for (int bi = 0; bi < 2; bi++) {
            ull macc = 0, acc = 0;
            #pragma unroll
            for (int k = 0; k < 10; k++) {
                fma2(macc, mp[bi * 10 + k], one);
                fma2(acc,  hp[bi * 10 + k], mp[bi * 10 + k]);
            }
            float a, b; upk2(macc, a, b);
            const float ms = a + b;
            upk2(acc, a, b);
            g[bi] = (ms > 0.f) ? (a + b) * (1.f / ms) : 0.f;
        }
        g2_sh[tid] = pk2(g[0], g[1]);
    }
    __syncthreads();

    // ---- fold at0's global half (scratch in dead B) ----
    fold_bias_v<100, 100, 100>(atw0, atb0, g2_sh, fold2, scratchB);
    __syncthreads();

    // ---- FUSED: m2w0 (A -> global m2h) + at0 (A -> B), one read of h1 ----
    dense_fused<100, 100>(m2w0, m2b0, atw0, fold2, A, m2h, B);
    __syncthreads();
    // A (h1) dead

    // ---- m2w1: global m2h -> h2 in C[0:50]; at1: B (ath) -> A (atH2)
    //      (independent after the fused barrier; back-to-back overlaps
    //       m2h global latency with at1's FFMA stream) ----
    dense<100, 50, 50, 2, false, 0>(m2w1, m2b1, m2h, C);
    dense<100, 100, 100, 4, true, 0>(atw1, atb1, B, A);
    __syncthreads();

    // ---- attention scores from A: i-split, 80 units x 50-step chains ----
    // partials in dead-B floats; then fused warp-level softmax
    // (warp 0 = batch 0, warp 1 = batch 1, lane = token; shfl butterfly sum).
    {
        float* part = B;   // ath consumed by at1 -> dead
        if (tid < 80) {
            const int half = tid / NI;        // 0: i 0..49, 1: i 50..99
            const int inst = tid % NI;
            const float* ip = A + inst + half * 50 * NI;
            float s = 0.f;
            #pragma unroll 5
            for (int i = 0; i < 50; i++)
                s = fmaf(ip[i * NI], atw2[half * 50 + i], s);
            part[tid] = s;
        }
        __syncthreads();
        if (tid < 64) {
            const int wrp = tid >> 5, lane = tid & 31;
            float se = 0.f;
            if (lane < NTOK) {
                const int inst = wrp * NTOK + lane;
                float s = part[inst] + part[inst + NI] + atb2[0];
                s *= mask_sh[inst];
                se = (s != 0.f) ? __expf(s) : 0.f;
            }
            float ssum = se;
            #pragma unroll
            for (int off = 16; off > 0; off >>= 1)
                ssum += __shfl_xor_sync(0xffffffffu, ssum, off);
            if (lane < NTOK)
                w_sh[wrp * NTOK + lane] = (ssum > 0.f) ? se / ssum : 0.f;
        }
    }
    __syncthreads();

    // ---- weighted sum of h2 (C) -> ws2 packed (b0,b1) ----
    if (tid < 50) {
        const ull* hp = reinterpret_cast<const ull*>(C + tid * NI);
        const ull* wp = reinterpret_cast<const ull*>(w_sh);
        float r[2];
        #pragma unroll
        for (int bi = 0; bi < 2; bi++) {
            ull acc = 0;
            #pragma unroll
            for (int k = 0; k < 10; k++) fma2(acc, hp[bi * 10 + k], wp[bi * 10 + k]);
            float a, b; upk2(acc, a, b);
            r[bi] = a + b;
        }
        ws2_sh[tid] = pk2(r[0], r[1]);
    }
    __syncthreads();

    // ---- fold hp0's weighted-sum half (scratch in dead B: ath consumed) ----
    fold_bias_v<50, 50, 100>(hpw0, hpb0, ws2_sh, fold2, scratchB);
    __syncthreads();

    // ---- head: hp0: C (h2) -> B (fold bias), hp1: B -> A ----
    dense<50, 100, 100, 4, true, 1>(hpw0, fold2, C, B);
    __syncthreads();
    dense<100, 100, 100, 4, true, 0>(hpw1, hpb1, B, A);
    __syncthreads();

    // ---- final 100 -> 7 from A: i-split, 280 units x 50-step chains ----
    // partials (packed token-pairs) in dead-B ulls; 140-unit STRIDED combine.
    {
        ull* part = scratchB;   // B (hpH) consumed by hp1 -> dead
        for (int t = tid; t < 280; t += TPB) {
            const int half = t / 140;       // 0: i 0..49, 1: i 50..99
            const int r    = t % 140;
            const int bi = r / 70;
            const int rr = r % 70;
            const int k  = rr / 7, j = rr % 7;
            ull acc = 0;
            const ull* ip = reinterpret_cast<const ull*>(A) + bi * 10 + k
                            + half * 50 * (NI / 2);
            const float* wp = hpw2 + half * 50 * 7 + j;
            #pragma unroll 4
            for (int i = 0; i < 50; i++) {
                const float w = wp[i * 7];
                fma2(acc, ip[i * (NI / 2)], pk2(w, w));
            }
            part[t] = acc;
        }
        __syncthreads();
        for (int t = tid; t < 140; t += TPB) {
            const int bi = t / 70;
            const int rr = t % 70;
            const int k  = rr / 7, j = rr % 7;
            float a0, b0v, a1, b1v;
            upk2(part[t], a0, b0v);
            upk2(part[t + 140], a1, b1v);
            const float bj = hpb2[j];
            float* ob = out + (size_t)(b0 + bi) * (NTOK * 7);
            ob[(2 * k)     * 7 + j] = a0 + a1 + bj;
            ob[(2 * k + 1) * 7 + j] = b0v + b1v + bj;
        }
    }
}

extern "C" void kernel_launch(void* const* d_in, const int* in_sizes, int n_in,
                              void* d_out, int out_size) {
    cudaFuncSetAttribute(sp_kernel,
                         cudaFuncAttributeMaxDynamicSharedMemorySize, SMEM_BYTES);
    cudaFuncSetAttribute(sp_kernel,
                         cudaFuncAttributePreferredSharedMemoryCarveout, 100);

    // state is the only huge tensor (B*20*14 elems); detect its position by size.
    int si, wb;
    if (in_sizes[0] > 1000000) { si = 0;        wb = 1; }
    else                       { si = n_in - 1; wb = 0; }
    const float* state = (const float*)d_in[si];
    const int B = in_sizes[si] / (NTOK * 14);

    sp_kernel<<<B / 2, TPB, SMEM_BYTES>>>(
        state,
        (const float*)d_in[wb + 0],  (const float*)d_in[wb + 1],
        (const float*)d_in[wb + 2],  (const float*)d_in[wb + 3],
        (const float*)d_in[wb + 4],  (const float*)d_in[wb + 5],
        (const float*)d_in[wb + 6],  (const float*)d_in[wb + 7],
        (const float*)d_in[wb + 8],  (const float*)d_in[wb + 9],
        (const float*)d_in[wb + 10], (const float*)d_in[wb + 11],
        (const float*)d_in[wb + 12], (const float*)d_in[wb + 13],
        (const float*)d_in[wb + 14], (const float*)d_in[wb + 15],
        (const float*)d_in[wb + 16], (const float*)d_in[wb + 17],
        (const float*)d_in[wb + 18], (const float*)d_in[wb + 19],
        (float*)d_out);
}